// round 1
// baseline (speedup 1.0000x reference)
#include <cuda_runtime.h>
#include <cuda_bf16.h>
#include <cstdint>

// Problem constants
#define BATCH   2
#define SEQ     4096
#define DIMM    1024
#define HEADS   16
#define DHEAD   64
#define ROWS    (BATCH*SEQ)          // 8192
#define DINNER  (HEADS*DHEAD)        // 1024

// ---------------- scratch (device globals; no allocation allowed) ----------
__device__ float g_xn[ROWS * DIMM];                       // 32MB
__device__ float g_q[BATCH * HEADS * SEQ * DHEAD];        // 32MB
__device__ float g_k[BATCH * HEADS * SEQ * DHEAD];        // 32MB
__device__ float g_v[BATCH * HEADS * SEQ * DHEAD];        // 32MB
__device__ float g_gate[ROWS * HEADS];                    // small (sigmoid applied)
__device__ float g_attn[ROWS * DIMM];                     // 32MB

// ---------------- RMSNorm: x / max(||x||,1e-12) * 32 * gamma ----------------
__global__ void rms_kernel(const float* __restrict__ x, const float* __restrict__ gamma) {
    int row = blockIdx.x;
    int t = threadIdx.x;                     // 256 threads, 4 floats each
    const float4* xr = (const float4*)(x + (size_t)row * DIMM);
    float4 a = xr[t];
    float ss = a.x*a.x + a.y*a.y + a.z*a.z + a.w*a.w;
    #pragma unroll
    for (int o = 16; o > 0; o >>= 1) ss += __shfl_down_sync(0xffffffffu, ss, o);
    __shared__ float red[8];
    __shared__ float snorm;
    if ((t & 31) == 0) red[t >> 5] = ss;
    __syncthreads();
    if (t == 0) {
        float s = 0.f;
        #pragma unroll
        for (int i = 0; i < 8; i++) s += red[i];
        snorm = 32.0f / fmaxf(sqrtf(s), 1e-12f);
    }
    __syncthreads();
    float sc = snorm;
    float4 g = ((const float4*)gamma)[t];
    float4 o4;
    o4.x = a.x * sc * g.x; o4.y = a.y * sc * g.y;
    o4.z = a.z * sc * g.z; o4.w = a.w * sc * g.w;
    ((float4*)(g_xn + (size_t)row * DIMM))[t] = o4;
}

// ---------------- SGEMM 128x128x8, 256 thr, 8x8 per thread (split-4 layout) --
// QKV=true: scatter C columns [3][H][64] into g_q/g_k/g_v with [b,h,S,d] layout.
template<bool QKV>
__global__ __launch_bounds__(256) void sgemm_kernel(
    const float* __restrict__ A, const float* __restrict__ Bm,
    float* __restrict__ C, int M, int N, int K)
{
    __shared__ float As[8][128];
    __shared__ float Bs[8][128];
    int tid = threadIdx.x;
    int bx = blockIdx.x, by = blockIdx.y;
    int tx = tid & 15, ty = tid >> 4;
    const int arow = tid >> 1, ac4 = (tid & 1) * 4;
    const int brow = tid >> 5, bc4 = (tid & 31) * 4;
    const float* Aptr = A + (size_t)(by * 128 + arow) * K + ac4;
    const float* Bptr = Bm + (size_t)brow * N + bx * 128 + bc4;

    float acc[8][8];
    #pragma unroll
    for (int i = 0; i < 8; i++)
        #pragma unroll
        for (int j = 0; j < 8; j++) acc[i][j] = 0.f;

    for (int k0 = 0; k0 < K; k0 += 8) {
        float4 a4 = *(const float4*)(Aptr + k0);
        float4 b4 = *(const float4*)(Bptr + (size_t)k0 * N);
        As[ac4 + 0][arow] = a4.x; As[ac4 + 1][arow] = a4.y;
        As[ac4 + 2][arow] = a4.z; As[ac4 + 3][arow] = a4.w;
        *(float4*)&Bs[brow][bc4] = b4;
        __syncthreads();
        #pragma unroll
        for (int kk = 0; kk < 8; kk++) {
            float af[8], bf[8];
            *(float4*)&af[0] = *(const float4*)&As[kk][ty * 4];
            *(float4*)&af[4] = *(const float4*)&As[kk][64 + ty * 4];
            *(float4*)&bf[0] = *(const float4*)&Bs[kk][tx * 4];
            *(float4*)&bf[4] = *(const float4*)&Bs[kk][64 + tx * 4];
            #pragma unroll
            for (int ii = 0; ii < 8; ii++)
                #pragma unroll
                for (int jj = 0; jj < 8; jj++)
                    acc[ii][jj] = fmaf(af[ii], bf[jj], acc[ii][jj]);
        }
        __syncthreads();
    }

    int cA = bx * 128 + tx * 4;
    int cB = cA + 64;
    #pragma unroll
    for (int ii = 0; ii < 8; ii++) {
        int r = by * 128 + ((ii < 4) ? (ty * 4 + ii) : (64 + ty * 4 + ii - 4));
        float4 vA = make_float4(acc[ii][0], acc[ii][1], acc[ii][2], acc[ii][3]);
        float4 vB = make_float4(acc[ii][4], acc[ii][5], acc[ii][6], acc[ii][7]);
        if (!QKV) {
            *(float4*)&C[(size_t)r * N + cA] = vA;
            *(float4*)&C[(size_t)r * N + cB] = vB;
        } else {
            int bb = r >> 12, s = r & 4095;
            {
                int which = cA >> 10, h = (cA >> 6) & 15, d = cA & 63;
                float* base = (which == 0) ? g_q : (which == 1) ? g_k : g_v;
                *(float4*)&base[(((size_t)(bb * HEADS + h)) * SEQ + s) * DHEAD + d] = vA;
            }
            {
                int which = cB >> 10, h = (cB >> 6) & 15, d = cB & 63;
                float* base = (which == 0) ? g_q : (which == 1) ? g_k : g_v;
                *(float4*)&base[(((size_t)(bb * HEADS + h)) * SEQ + s) * DHEAD + d] = vB;
            }
        }
    }
}

// ---------------- gates = sigmoid(xn @ W_gates + b) ------------------------
__global__ void gates_kernel(const float* __restrict__ Wg, const float* __restrict__ bg) {
    int row = blockIdx.x;
    int t = threadIdx.x;                 // 128 threads: 16 heads x 8 lanes
    int h = t >> 3, lane8 = t & 7;
    const float* xr = g_xn + (size_t)row * DIMM;
    float sum = 0.f;
    for (int j = lane8; j < DIMM; j += 8) sum += xr[j] * Wg[j * HEADS + h];
    sum += __shfl_down_sync(0xffffffffu, sum, 4, 8);
    sum += __shfl_down_sync(0xffffffffu, sum, 2, 8);
    sum += __shfl_down_sync(0xffffffffu, sum, 1, 8);
    if (lane8 == 0) {
        float v = sum + bg[h];
        g_gate[row * HEADS + h] = 1.f / (1.f + __expf(-v));
    }
}

// ---------------- sliding-window attention --------------------------------
// Effective mask: key j valid iff  j >= 0  &&  0 <= i - j <= 256.
// CTA = 64 queries for one (batch, head). 5 aligned 64-key chunks.
// Static smem exactly 48KB: K(16K) + V(16K) + swizzled scores(16K).
__global__ __launch_bounds__(64) void attn_kernel() {
    int tile = blockIdx.x;   // 0..63 -> q0 = tile*64
    int h    = blockIdx.y;   // 0..15
    int bb   = blockIdx.z;   // 0..1
    int i    = threadIdx.x;  // 0..63 (query row within tile)
    int q0   = tile * 64;

    __shared__ float4 Ks[64 * 16];
    __shared__ float4 Vs[64 * 16];
    __shared__ float  sc[64 * 64];   // XOR-swizzled per-row score rows

    size_t base = ((size_t)(bb * HEADS + h)) * SEQ * DHEAD;
    const float4* qg = (const float4*)(g_q + base + (size_t)(q0 + i) * DHEAD);

    float4 qf[16];
    #pragma unroll
    for (int dd = 0; dd < 16; dd++) {
        float4 t = qg[dd];
        t.x *= 0.125f; t.y *= 0.125f; t.z *= 0.125f; t.w *= 0.125f;  // 1/sqrt(64)
        qf[dd] = t;
    }

    float m = -1e30f, l = 0.f;
    float4 acc[16];
    #pragma unroll
    for (int dd = 0; dd < 16; dd++) acc[dd] = make_float4(0.f, 0.f, 0.f, 0.f);

    const int sw = i & 31;   // bank swizzle key
    float* srow = &sc[i * 64];

    for (int c = 0; c < 5; c++) {
        int ks = q0 - 256 + c * 64;
        if (ks < 0) continue;                         // key_exists (j >= 0)
        __syncthreads();                              // protect Ks/Vs reuse
        const float4* kg = (const float4*)(g_k + base + (size_t)ks * DHEAD);
        const float4* vg = (const float4*)(g_v + base + (size_t)ks * DHEAD);
        for (int idx = i; idx < 1024; idx += 64) { Ks[idx] = kg[idx]; Vs[idx] = vg[idx]; }
        __syncthreads();

        // scores for my row
        float mc = -1e30f;
        for (int j = 0; j < 64; j++) {
            bool valid = (c == 0) ? (j >= i) : (c == 4) ? (j <= i) : true;
            const float4* kr = &Ks[j * 16];
            float4 s4 = make_float4(0.f, 0.f, 0.f, 0.f);
            #pragma unroll
            for (int dd = 0; dd < 16; dd++) {
                float4 kf = kr[dd];
                s4.x = fmaf(qf[dd].x, kf.x, s4.x);
                s4.y = fmaf(qf[dd].y, kf.y, s4.y);
                s4.z = fmaf(qf[dd].z, kf.z, s4.z);
                s4.w = fmaf(qf[dd].w, kf.w, s4.w);
            }
            float s = (s4.x + s4.y) + (s4.z + s4.w);
            srow[j ^ sw] = s;
            if (valid && s > mc) mc = s;
        }

        float mnew = fmaxf(m, mc);
        float corr = __expf(m - mnew);
        l *= corr;
        #pragma unroll
        for (int dd = 0; dd < 16; dd++) {
            acc[dd].x *= corr; acc[dd].y *= corr; acc[dd].z *= corr; acc[dd].w *= corr;
        }
        for (int j = 0; j < 64; j++) {
            bool valid = (c == 0) ? (j >= i) : (c == 4) ? (j <= i) : true;
            float p = valid ? __expf(srow[j ^ sw] - mnew) : 0.f;
            l += p;
            const float4* vr = &Vs[j * 16];
            #pragma unroll
            for (int dd = 0; dd < 16; dd++) {
                float4 vv = vr[dd];
                acc[dd].x = fmaf(p, vv.x, acc[dd].x);
                acc[dd].y = fmaf(p, vv.y, acc[dd].y);
                acc[dd].z = fmaf(p, vv.z, acc[dd].z);
                acc[dd].w = fmaf(p, vv.w, acc[dd].w);
            }
        }
        m = mnew;
    }

    int row = bb * SEQ + q0 + i;
    float g = g_gate[row * HEADS + h];
    float inv = g / l;
    float4* out = (float4*)(g_attn + (size_t)row * DIMM + h * DHEAD);
    #pragma unroll
    for (int dd = 0; dd < 16; dd++) {
        float4 a = acc[dd];
        out[dd] = make_float4(a.x * inv, a.y * inv, a.z * inv, a.w * inv);
    }
}

// ---------------- launch ----------------------------------------------------
extern "C" void kernel_launch(void* const* d_in, const int* in_sizes, int n_in,
                              void* d_out, int out_size) {
    const float* x     = (const float*)d_in[0];
    const float* gamma = (const float*)d_in[1];
    const float* Wqkv  = (const float*)d_in[2];
    const float* Wg    = (const float*)d_in[3];
    const float* bg    = (const float*)d_in[4];
    const float* Wout  = (const float*)d_in[5];

    float *xn_p, *attn_p;
    cudaGetSymbolAddress((void**)&xn_p, g_xn);
    cudaGetSymbolAddress((void**)&attn_p, g_attn);

    rms_kernel<<<ROWS, 256>>>(x, gamma);
    sgemm_kernel<true><<<dim3(3 * DINNER / 128, ROWS / 128), 256>>>(
        xn_p, Wqkv, nullptr, ROWS, 3 * DINNER, DIMM);
    gates_kernel<<<ROWS, 128>>>(Wg, bg);
    attn_kernel<<<dim3(SEQ / 256 * 4, HEADS, BATCH), 64>>>();
    sgemm_kernel<false><<<dim3(DIMM / 128, ROWS / 128), 256>>>(
        attn_p, Wout, (float*)d_out, ROWS, DIMM, DIMM);
}

// round 3
// speedup vs baseline: 1.7195x; 1.7195x over previous
#include <cuda_runtime.h>
#include <cuda_bf16.h>
#include <cstdint>

// Problem constants
#define BATCH   2
#define SEQ     4096
#define DIMM    1024
#define HEADS   16
#define DHEAD   64
#define ROWS    (BATCH*SEQ)          // 8192
#define DINNER  (HEADS*DHEAD)        // 1024

// ---------------- scratch (device globals; no allocation allowed) ----------
__device__ float g_xn[ROWS * DIMM];                        // f32 (gates)
__device__ __nv_bfloat16 g_xn_hi[ROWS * DIMM];
__device__ __nv_bfloat16 g_xn_lo[ROWS * DIMM];
__device__ float g_q[BATCH * HEADS * SEQ * DHEAD];
__device__ float g_k[BATCH * HEADS * SEQ * DHEAD];
__device__ float g_v[BATCH * HEADS * SEQ * DHEAD];
__device__ float g_gate[ROWS * HEADS];
__device__ __nv_bfloat16 g_attn_hi[ROWS * DINNER];
__device__ __nv_bfloat16 g_attn_lo[ROWS * DINNER];
__device__ __nv_bfloat16 g_wqkv_hi[3 * DINNER * DIMM];     // [3072,1024] K-major
__device__ __nv_bfloat16 g_wqkv_lo[3 * DINNER * DIMM];
__device__ __nv_bfloat16 g_wout_hi[DIMM * DINNER];         // [1024,1024] K-major
__device__ __nv_bfloat16 g_wout_lo[DIMM * DINNER];

// ================= base-ISA helpers (no tcgen05!) ===========================
__device__ __forceinline__ uint32_t smem_u32(const void* p) {
    uint32_t a;
    asm("{ .reg .u64 t; cvta.to.shared.u64 t, %1; cvt.u32.u64 %0, t; }" : "=r"(a) : "l"(p));
    return a;
}
__device__ __forceinline__ void cp16(uint32_t s, const void* g) {
    asm volatile("cp.async.cg.shared.global [%0], [%1], 16;" :: "r"(s), "l"(g));
}
#define CP_COMMIT() asm volatile("cp.async.commit_group;" ::: "memory")
#define CP_WAIT1()  asm volatile("cp.async.wait_group 1;" ::: "memory")
#define CP_WAIT0()  asm volatile("cp.async.wait_group 0;" ::: "memory")

__device__ __forceinline__ void ldsm4(uint32_t& r0, uint32_t& r1, uint32_t& r2, uint32_t& r3, uint32_t a) {
    asm volatile("ldmatrix.sync.aligned.m8n8.x4.shared.b16 {%0,%1,%2,%3}, [%4];"
                 : "=r"(r0), "=r"(r1), "=r"(r2), "=r"(r3) : "r"(a));
}
__device__ __forceinline__ void mma16816(float* d, const uint32_t* a, const uint32_t* b) {
    asm volatile("mma.sync.aligned.m16n8k16.row.col.f32.bf16.bf16.f32 "
                 "{%0,%1,%2,%3}, {%4,%5,%6,%7}, {%8,%9}, {%0,%1,%2,%3};"
                 : "+f"(d[0]), "+f"(d[1]), "+f"(d[2]), "+f"(d[3])
                 : "r"(a[0]), "r"(a[1]), "r"(a[2]), "r"(a[3]), "r"(b[0]), "r"(b[1]));
}

// ---------------- RMSNorm: also emits bf16 hi/lo split ---------------------
__global__ void rms_kernel(const float* __restrict__ x, const float* __restrict__ gamma) {
    int row = blockIdx.x;
    int t = threadIdx.x;                     // 256 threads, 4 floats each
    const float4* xr = (const float4*)(x + (size_t)row * DIMM);
    float4 a = xr[t];
    float ss = a.x*a.x + a.y*a.y + a.z*a.z + a.w*a.w;
    #pragma unroll
    for (int o = 16; o > 0; o >>= 1) ss += __shfl_down_sync(0xffffffffu, ss, o);
    __shared__ float red[8];
    __shared__ float snorm;
    if ((t & 31) == 0) red[t >> 5] = ss;
    __syncthreads();
    if (t == 0) {
        float s = 0.f;
        #pragma unroll
        for (int i = 0; i < 8; i++) s += red[i];
        snorm = 32.0f / fmaxf(sqrtf(s), 1e-12f);
    }
    __syncthreads();
    float sc = snorm;
    float4 g = ((const float4*)gamma)[t];
    float4 o4;
    o4.x = a.x * sc * g.x; o4.y = a.y * sc * g.y;
    o4.z = a.z * sc * g.z; o4.w = a.w * sc * g.w;
    ((float4*)(g_xn + (size_t)row * DIMM))[t] = o4;

    float f[4] = {o4.x, o4.y, o4.z, o4.w};
    __nv_bfloat16 hb[4]; float lo[4];
    #pragma unroll
    for (int i = 0; i < 4; i++) {
        hb[i] = __float2bfloat16(f[i]);
        lo[i] = f[i] - __bfloat162float(hb[i]);
    }
    __nv_bfloat162* ph = (__nv_bfloat162*)(g_xn_hi + (size_t)row * DIMM);
    __nv_bfloat162* pl = (__nv_bfloat162*)(g_xn_lo + (size_t)row * DIMM);
    __nv_bfloat162 h01; h01.x = hb[0]; h01.y = hb[1];
    __nv_bfloat162 h23; h23.x = hb[2]; h23.y = hb[3];
    ph[2*t]   = h01;
    ph[2*t+1] = h23;
    pl[2*t]   = __floats2bfloat162_rn(lo[0], lo[1]);
    pl[2*t+1] = __floats2bfloat162_rn(lo[2], lo[3]);
}

// ---------------- weight transpose + hi/lo split ---------------------------
// W [1024, N] f32 row-major  ->  Wt_hi/lo [N, 1024] bf16 (K-major)
__global__ void transpose_split(const float* __restrict__ W,
                                __nv_bfloat16* __restrict__ hi,
                                __nv_bfloat16* __restrict__ lo, int N) {
    __shared__ float t[32][33];
    int tx = threadIdx.x, ty = threadIdx.y;
    int x = blockIdx.x * 32 + tx;
    int y0 = blockIdx.y * 32;
    #pragma unroll
    for (int r = ty; r < 32; r += 8)
        t[r][tx] = W[(size_t)(y0 + r) * N + x];
    __syncthreads();
    #pragma unroll
    for (int r = 0; r < 4; r++) {
        int a = ty + r * 8;
        float v = t[tx][a];
        __nv_bfloat16 h = __float2bfloat16(v);
        size_t o = (size_t)(blockIdx.x * 32 + a) * DIMM + y0 + tx;
        hi[o] = h;
        lo[o] = __float2bfloat16(v - __bfloat162float(h));
    }
}

// ---------------- bf16x3 mma.sync GEMM 128x128, KB=32, double-buffered -----
// A [M,1024] hi/lo bf16 row-major; B [N,1024] hi/lo bf16 (K-major).
// MODE 0: QKV -> scatter columns [3][H][64] into g_q/g_k/g_v [b,h,S,d] (f32)
// MODE 1: plain C [M,1024] f32
#define PITCHB      80                       // bytes per smem row (40 bf16)
#define MAT_BYTES   (128 * PITCHB)           // 10240
#define STG_BYTES   (4 * MAT_BYTES)          // 40960 (Ahi,Alo,Bhi,Blo)
#define GSMEM_TOTAL (2 * STG_BYTES)          // 81920

template<int MODE>
__global__ __launch_bounds__(256) void mma_gemm_kernel(
    const __nv_bfloat16* __restrict__ Ahi, const __nv_bfloat16* __restrict__ Alo,
    const __nv_bfloat16* __restrict__ Bhi, const __nv_bfloat16* __restrict__ Blo,
    float* __restrict__ C)
{
    extern __shared__ char smem[];
    const uint32_t sb = smem_u32(smem);
    const int tid = threadIdx.x;
    const int lane = tid & 31, wid = tid >> 5;
    const int wm = wid >> 2, wn = wid & 3;       // 2 x 4 warp grid
    const int bx = blockIdx.x, by = blockIdx.y;

    const size_t aBase = (size_t)(by * 128) * DIMM;
    const size_t bBase = (size_t)(bx * 128) * DIMM;
    const __nv_bfloat16* gmat[4] = {Ahi + aBase, Alo + aBase, Bhi + bBase, Blo + bBase};

    // cp.async mapping: 2048 16B-chunks per stage, 8 per thread
    int ld_mat[8], ld_row[8], ld_ch[8];
    #pragma unroll
    for (int i = 0; i < 8; i++) {
        int idx = tid + i * 256;
        ld_mat[i] = idx >> 9;
        int rem = idx & 511;
        ld_row[i] = rem >> 2;
        ld_ch[i]  = rem & 3;
    }

    float acc[4][4][4];
    #pragma unroll
    for (int mt = 0; mt < 4; mt++)
        #pragma unroll
        for (int nt = 0; nt < 4; nt++)
            #pragma unroll
            for (int r = 0; r < 4; r++) acc[mt][nt][r] = 0.f;

    // ldmatrix per-lane address components
    const int quad = lane >> 3, l7 = lane & 7;
    const int a_row = (quad & 1) * 8 + l7;       // within 16-row A tile
    const int a_ch  = quad >> 1;                 // k chunk (+0/+1)
    const int b_row = (quad >> 1) * 8 + l7;      // within 16-row (n) B pair
    const int b_ch  = quad & 1;

    auto load_stage = [&](int kb, int buf) {
        uint32_t s0 = sb + buf * STG_BYTES;
        #pragma unroll
        for (int i = 0; i < 8; i++) {
            const __nv_bfloat16* g = gmat[ld_mat[i]] + (size_t)ld_row[i] * DIMM + kb * 32 + ld_ch[i] * 8;
            uint32_t s = s0 + ld_mat[i] * MAT_BYTES + ld_row[i] * PITCHB + ld_ch[i] * 16;
            cp16(s, g);
        }
        CP_COMMIT();
    };

    load_stage(0, 0);
    load_stage(1, 1);

    const int NKB = DIMM / 32;   // 32
    for (int kb = 0; kb < NKB; kb++) {
        if (kb < NKB - 1) { CP_WAIT1(); } else { CP_WAIT0(); }
        __syncthreads();
        const int buf = kb & 1;
        const uint32_t s0 = sb + buf * STG_BYTES;
        const uint32_t sAh = s0 + 0 * MAT_BYTES, sAl = s0 + 1 * MAT_BYTES;
        const uint32_t sBh = s0 + 2 * MAT_BYTES, sBl = s0 + 3 * MAT_BYTES;

        #pragma unroll
        for (int ks = 0; ks < 2; ks++) {
            uint32_t ah[4][4], al[4][4], bh[2][4], bl[2][4];
            #pragma unroll
            for (int mt = 0; mt < 4; mt++) {
                uint32_t off = (uint32_t)(wm * 64 + mt * 16 + a_row) * PITCHB + (ks * 2 + a_ch) * 16;
                ldsm4(ah[mt][0], ah[mt][1], ah[mt][2], ah[mt][3], sAh + off);
                ldsm4(al[mt][0], al[mt][1], al[mt][2], al[mt][3], sAl + off);
            }
            #pragma unroll
            for (int np = 0; np < 2; np++) {
                uint32_t off = (uint32_t)(wn * 32 + np * 16 + b_row) * PITCHB + (ks * 2 + b_ch) * 16;
                ldsm4(bh[np][0], bh[np][1], bh[np][2], bh[np][3], sBh + off);
                ldsm4(bl[np][0], bl[np][1], bl[np][2], bl[np][3], sBl + off);
            }
            #pragma unroll
            for (int mt = 0; mt < 4; mt++) {
                #pragma unroll
                for (int np = 0; np < 2; np++) {
                    #pragma unroll
                    for (int half = 0; half < 2; half++) {
                        int nt = np * 2 + half;
                        mma16816(acc[mt][nt], ah[mt], &bh[np][half * 2]);
                        mma16816(acc[mt][nt], ah[mt], &bl[np][half * 2]);
                        mma16816(acc[mt][nt], al[mt], &bh[np][half * 2]);
                    }
                }
            }
        }
        __syncthreads();
        if (kb + 2 < NKB) load_stage(kb + 2, buf);
    }

    // epilogue
    #pragma unroll
    for (int mt = 0; mt < 4; mt++) {
        #pragma unroll
        for (int nt = 0; nt < 4; nt++) {
            #pragma unroll
            for (int rp = 0; rp < 2; rp++) {
                int row = by * 128 + wm * 64 + mt * 16 + (lane >> 2) + rp * 8;
                int col = bx * 128 + wn * 32 + nt * 8 + (lane & 3) * 2;
                float2 v = make_float2(acc[mt][nt][rp * 2], acc[mt][nt][rp * 2 + 1]);
                if (MODE == 0) {
                    int which = col >> 10, h = (col >> 6) & 15, d0 = col & 63;
                    int bb = row >> 12, s = row & 4095;
                    float* base = (which == 0) ? g_q : (which == 1) ? g_k : g_v;
                    *(float2*)&base[(((size_t)(bb * HEADS + h)) * SEQ + s) * DHEAD + d0] = v;
                } else {
                    *(float2*)&C[(size_t)row * DIMM + col] = v;
                }
            }
        }
    }
}

// ---------------- gates = sigmoid(xn @ W_gates + b) ------------------------
__global__ void gates_kernel(const float* __restrict__ Wg, const float* __restrict__ bg) {
    int row = blockIdx.x;
    int t = threadIdx.x;
    int h = t >> 3, lane8 = t & 7;
    const float* xr = g_xn + (size_t)row * DIMM;
    float sum = 0.f;
    for (int j = lane8; j < DIMM; j += 8) sum += xr[j] * Wg[j * HEADS + h];
    sum += __shfl_down_sync(0xffffffffu, sum, 4, 8);
    sum += __shfl_down_sync(0xffffffffu, sum, 2, 8);
    sum += __shfl_down_sync(0xffffffffu, sum, 1, 8);
    if (lane8 == 0) {
        float v = sum + bg[h];
        g_gate[row * HEADS + h] = 1.f / (1.f + __expf(-v));
    }
}

// ---------------- sliding-window attention (register-chunk softmax) --------
__global__ __launch_bounds__(64) void attn_kernel() {
    int tile = blockIdx.x;
    int h    = blockIdx.y;
    int bb   = blockIdx.z;
    int i    = threadIdx.x;
    int q0   = tile * 64;

    __shared__ float4 Ks[64 * 16];
    __shared__ float4 Vs[64 * 16];

    size_t base = ((size_t)(bb * HEADS + h)) * SEQ * DHEAD;
    const float4* qg = (const float4*)(g_q + base + (size_t)(q0 + i) * DHEAD);

    float4 qf[16];
    #pragma unroll
    for (int dd = 0; dd < 16; dd++) {
        float4 t = qg[dd];
        t.x *= 0.125f; t.y *= 0.125f; t.z *= 0.125f; t.w *= 0.125f;
        qf[dd] = t;
    }

    float m = -1e30f, l = 0.f;
    float4 acc[16];
    #pragma unroll
    for (int dd = 0; dd < 16; dd++) acc[dd] = make_float4(0.f, 0.f, 0.f, 0.f);

    for (int c = 0; c < 5; c++) {
        int ks = q0 - 256 + c * 64;
        if (ks < 0) continue;
        __syncthreads();
        const float4* kg = (const float4*)(g_k + base + (size_t)ks * DHEAD);
        const float4* vg = (const float4*)(g_v + base + (size_t)ks * DHEAD);
        for (int idx = i; idx < 1024; idx += 64) { Ks[idx] = kg[idx]; Vs[idx] = vg[idx]; }
        __syncthreads();

        for (int jt = 0; jt < 4; jt++) {
            float s[16];
            float mc = -1e30f;
            #pragma unroll
            for (int jj = 0; jj < 16; jj++) {
                int j = jt * 16 + jj;
                bool valid = (c == 0) ? (j >= i) : (c == 4) ? (j <= i) : true;
                const float4* kr = &Ks[j * 16];
                float4 s4 = make_float4(0.f, 0.f, 0.f, 0.f);
                #pragma unroll
                for (int dd = 0; dd < 16; dd++) {
                    float4 kf = kr[dd];
                    s4.x = fmaf(qf[dd].x, kf.x, s4.x);
                    s4.y = fmaf(qf[dd].y, kf.y, s4.y);
                    s4.z = fmaf(qf[dd].z, kf.z, s4.z);
                    s4.w = fmaf(qf[dd].w, kf.w, s4.w);
                }
                float sv = (s4.x + s4.y) + (s4.z + s4.w);
                s[jj] = valid ? sv : -1e30f;
                if (valid && sv > mc) mc = sv;
            }
            float mnew = fmaxf(m, mc);
            float corr = __expf(m - mnew);
            l *= corr;
            #pragma unroll
            for (int dd = 0; dd < 16; dd++) {
                acc[dd].x *= corr; acc[dd].y *= corr; acc[dd].z *= corr; acc[dd].w *= corr;
            }
            #pragma unroll
            for (int jj = 0; jj < 16; jj++) {
                int j = jt * 16 + jj;
                bool valid = (c == 0) ? (j >= i) : (c == 4) ? (j <= i) : true;
                float p = valid ? __expf(s[jj] - mnew) : 0.f;
                l += p;
                const float4* vr = &Vs[j * 16];
                #pragma unroll
                for (int dd = 0; dd < 16; dd++) {
                    float4 vv = vr[dd];
                    acc[dd].x = fmaf(p, vv.x, acc[dd].x);
                    acc[dd].y = fmaf(p, vv.y, acc[dd].y);
                    acc[dd].z = fmaf(p, vv.z, acc[dd].z);
                    acc[dd].w = fmaf(p, vv.w, acc[dd].w);
                }
            }
            m = mnew;
        }
    }

    int row = bb * SEQ + q0 + i;
    float g = g_gate[row * HEADS + h];
    float inv = g / l;
    __nv_bfloat162* oh = (__nv_bfloat162*)(g_attn_hi + (size_t)row * DINNER + h * DHEAD);
    __nv_bfloat162* ol = (__nv_bfloat162*)(g_attn_lo + (size_t)row * DINNER + h * DHEAD);
    #pragma unroll
    for (int dd = 0; dd < 16; dd++) {
        float4 a = acc[dd];
        float f[4] = {a.x * inv, a.y * inv, a.z * inv, a.w * inv};
        __nv_bfloat16 hb[4]; float lo[4];
        #pragma unroll
        for (int q = 0; q < 4; q++) {
            hb[q] = __float2bfloat16(f[q]);
            lo[q] = f[q] - __bfloat162float(hb[q]);
        }
        __nv_bfloat162 h01; h01.x = hb[0]; h01.y = hb[1];
        __nv_bfloat162 h23; h23.x = hb[2]; h23.y = hb[3];
        oh[2*dd]   = h01;
        oh[2*dd+1] = h23;
        ol[2*dd]   = __floats2bfloat162_rn(lo[0], lo[1]);
        ol[2*dd+1] = __floats2bfloat162_rn(lo[2], lo[3]);
    }
}

// ---------------- launch ----------------------------------------------------
extern "C" void kernel_launch(void* const* d_in, const int* in_sizes, int n_in,
                              void* d_out, int out_size) {
    const float* x     = (const float*)d_in[0];
    const float* gamma = (const float*)d_in[1];
    const float* Wqkv  = (const float*)d_in[2];
    const float* Wg    = (const float*)d_in[3];
    const float* bg    = (const float*)d_in[4];
    const float* Wout  = (const float*)d_in[5];

    __nv_bfloat16 *xn_hi, *xn_lo, *wqkv_hi, *wqkv_lo, *wout_hi, *wout_lo, *attn_hi, *attn_lo;
    cudaGetSymbolAddress((void**)&xn_hi,   g_xn_hi);
    cudaGetSymbolAddress((void**)&xn_lo,   g_xn_lo);
    cudaGetSymbolAddress((void**)&wqkv_hi, g_wqkv_hi);
    cudaGetSymbolAddress((void**)&wqkv_lo, g_wqkv_lo);
    cudaGetSymbolAddress((void**)&wout_hi, g_wout_hi);
    cudaGetSymbolAddress((void**)&wout_lo, g_wout_lo);
    cudaGetSymbolAddress((void**)&attn_hi, g_attn_hi);
    cudaGetSymbolAddress((void**)&attn_lo, g_attn_lo);

    cudaFuncSetAttribute(mma_gemm_kernel<0>, cudaFuncAttributeMaxDynamicSharedMemorySize, GSMEM_TOTAL);
    cudaFuncSetAttribute(mma_gemm_kernel<1>, cudaFuncAttributeMaxDynamicSharedMemorySize, GSMEM_TOTAL);

    transpose_split<<<dim3(3 * DINNER / 32, DIMM / 32), dim3(32, 8)>>>(Wqkv, wqkv_hi, wqkv_lo, 3 * DINNER);
    transpose_split<<<dim3(DIMM / 32, DIMM / 32), dim3(32, 8)>>>(Wout, wout_hi, wout_lo, DIMM);
    rms_kernel<<<ROWS, 256>>>(x, gamma);
    mma_gemm_kernel<0><<<dim3(3 * DINNER / 128, ROWS / 128), 256, GSMEM_TOTAL>>>(
        xn_hi, xn_lo, wqkv_hi, wqkv_lo, nullptr);
    gates_kernel<<<ROWS, 128>>>(Wg, bg);
    attn_kernel<<<dim3(SEQ / 64, HEADS, BATCH), 64>>>();
    mma_gemm_kernel<1><<<dim3(DIMM / 128, ROWS / 128), 256, GSMEM_TOTAL>>>(
        attn_hi, attn_lo, wout_hi, wout_lo, (float*)d_out);
}

// round 10
// speedup vs baseline: 5.0708x; 2.9490x over previous
#include <cuda_runtime.h>
#include <cuda_fp16.h>
#include <cstdint>

#define BATCH   2
#define SEQ     4096
#define DIMM    1024
#define HEADS   16
#define DHEAD   64
#define ROWS    (BATCH*SEQ)
#define DINNER  (HEADS*DHEAD)

__device__ __half g_xn_h[ROWS * DIMM];
__device__ __half g_qh[BATCH * HEADS * SEQ * DHEAD];
__device__ __half g_kh[BATCH * HEADS * SEQ * DHEAD];
__device__ __half g_vh[BATCH * HEADS * SEQ * DHEAD];
__device__ float  g_gate[ROWS * HEADS];
__device__ __half g_attn_h[ROWS * DINNER];
__device__ __half g_wqkv_h[3 * DINNER * DIMM];
__device__ __half g_wout_h[DIMM * DINNER];

__device__ __forceinline__ uint32_t smem_u32(const void* p) {
    uint32_t a;
    asm("{ .reg .u64 t; cvta.to.shared.u64 t, %1; cvt.u32.u64 %0, t; }" : "=r"(a) : "l"(p));
    return a;
}
__device__ __forceinline__ void cp16(uint32_t s, const void* g) {
    asm volatile("cp.async.cg.shared.global [%0], [%1], 16;" :: "r"(s), "l"(g));
}
#define CP_COMMIT() asm volatile("cp.async.commit_group;" ::: "memory")
#define CP_WAIT1()  asm volatile("cp.async.wait_group 1;" ::: "memory")
#define CP_WAIT0()  asm volatile("cp.async.wait_group 0;" ::: "memory")

__device__ __forceinline__ void ldsm4(uint32_t& r0, uint32_t& r1, uint32_t& r2, uint32_t& r3, uint32_t a) {
    asm volatile("ldmatrix.sync.aligned.m8n8.x4.shared.b16 {%0,%1,%2,%3}, [%4];"
                 : "=r"(r0), "=r"(r1), "=r"(r2), "=r"(r3) : "r"(a));
}
__device__ __forceinline__ void ldsm4t(uint32_t& r0, uint32_t& r1, uint32_t& r2, uint32_t& r3, uint32_t a) {
    asm volatile("ldmatrix.sync.aligned.m8n8.x4.trans.shared.b16 {%0,%1,%2,%3}, [%4];"
                 : "=r"(r0), "=r"(r1), "=r"(r2), "=r"(r3) : "r"(a));
}
__device__ __forceinline__ void mma16816(float* d, const uint32_t* a, const uint32_t* b) {
    asm volatile("mma.sync.aligned.m16n8k16.row.col.f32.f16.f16.f32 "
                 "{%0,%1,%2,%3}, {%4,%5,%6,%7}, {%8,%9}, {%0,%1,%2,%3};"
                 : "+f"(d[0]), "+f"(d[1]), "+f"(d[2]), "+f"(d[3])
                 : "r"(a[0]), "r"(a[1]), "r"(a[2]), "r"(a[3]), "r"(b[0]), "r"(b[1]));
}
__device__ __forceinline__ uint32_t packh2(float a, float b) {
    __half2 h = __floats2half2_rn(a, b);
    return *(uint32_t*)&h;
}

__global__ void rms_kernel(const float* __restrict__ x, const float* __restrict__ gamma) {
    int row = blockIdx.x;
    int t = threadIdx.x;
    const float4* xr = (const float4*)(x + (size_t)row * DIMM);
    float4 a = xr[t];
    float ss = a.x*a.x + a.y*a.y + a.z*a.z + a.w*a.w;
    #pragma unroll
    for (int o = 16; o > 0; o >>= 1) ss += __shfl_down_sync(0xffffffffu, ss, o);
    __shared__ float red[8];
    __shared__ float snorm;
    if ((t & 31) == 0) red[t >> 5] = ss;
    __syncthreads();
    if (t == 0) {
        float s = 0.f;
        #pragma unroll
        for (int i = 0; i < 8; i++) s += red[i];
        snorm = 32.0f / fmaxf(sqrtf(s), 1e-12f);
    }
    __syncthreads();
    float sc = snorm;
    float4 g = ((const float4*)gamma)[t];
    __half2* ph = (__half2*)(g_xn_h + (size_t)row * DIMM);
    ph[2*t]   = __floats2half2_rn(a.x * sc * g.x, a.y * sc * g.y);
    ph[2*t+1] = __floats2half2_rn(a.z * sc * g.z, a.w * sc * g.w);
}

__global__ void transpose_h(const float* __restrict__ W, __half* __restrict__ out, int N) {
    __shared__ float t[32][33];
    int tx = threadIdx.x, ty = threadIdx.y;
    int x = blockIdx.x * 32 + tx;
    int y0 = blockIdx.y * 32;
    #pragma unroll
    for (int r = ty; r < 32; r += 8)
        t[r][tx] = W[(size_t)(y0 + r) * N + x];
    __syncthreads();
    #pragma unroll
    for (int r = 0; r < 4; r++) {
        int a = ty + r * 8;
        out[(size_t)(blockIdx.x * 32 + a) * DIMM + y0 + tx] = __float2half_rn(t[tx][a]);
    }
}

#define PITCHB      80
#define MAT_BYTES   (128 * PITCHB)
#define STG_BYTES   (2 * MAT_BYTES)
#define GSMEM_TOTAL (2 * STG_BYTES)

template<int MODE>
__global__ __launch_bounds__(256) void mma_gemm_kernel(
    const __half* __restrict__ A, const __half* __restrict__ B,
    float* __restrict__ C)
{
    extern __shared__ char smem[];
    const uint32_t sb = smem_u32(smem);
    const int tid = threadIdx.x;
    const int lane = tid & 31, wid = tid >> 5;
    const int wm = wid >> 2, wn = wid & 3;
    const int bx = blockIdx.x, by = blockIdx.y;

    const __half* gmat[2] = {A + (size_t)(by * 128) * DIMM, B + (size_t)(bx * 128) * DIMM};

    int ld_mat[4], ld_row[4], ld_ch[4];
    #pragma unroll
    for (int i = 0; i < 4; i++) {
        int idx = tid + i * 256;
        ld_mat[i] = idx >> 9;
        int rem = idx & 511;
        ld_row[i] = rem >> 2;
        ld_ch[i]  = rem & 3;
    }

    float acc[4][4][4];
    #pragma unroll
    for (int mt = 0; mt < 4; mt++)
        #pragma unroll
        for (int nt = 0; nt < 4; nt++)
            #pragma unroll
            for (int r = 0; r < 4; r++) acc[mt][nt][r] = 0.f;

    const int quad = lane >> 3, l7 = lane & 7;
    const int a_row = (quad & 1) * 8 + l7;
    const int a_ch  = quad >> 1;
    const int b_row = (quad >> 1) * 8 + l7;
    const int b_ch  = quad & 1;

    auto load_stage = [&](int kb, int buf) {
        uint32_t s0 = sb + buf * STG_BYTES;
        #pragma unroll
        for (int i = 0; i < 4; i++) {
            const __half* g = gmat[ld_mat[i]] + (size_t)ld_row[i] * DIMM + kb * 32 + ld_ch[i] * 8;
            cp16(s0 + ld_mat[i] * MAT_BYTES + ld_row[i] * PITCHB + ld_ch[i] * 16, g);
        }
        CP_COMMIT();
    };

    load_stage(0, 0);
    load_stage(1, 1);

    const int NKB = DIMM / 32;
    for (int kb = 0; kb < NKB; kb++) {
        if (kb < NKB - 1) { CP_WAIT1(); } else { CP_WAIT0(); }
        __syncthreads();
        const uint32_t s0 = sb + (kb & 1) * STG_BYTES;
        const uint32_t sA = s0, sB = s0 + MAT_BYTES;

        #pragma unroll
        for (int ks = 0; ks < 2; ks++) {
            uint32_t ah[4][4], bh[2][4];
            #pragma unroll
            for (int mt = 0; mt < 4; mt++) {
                uint32_t off = (uint32_t)(wm * 64 + mt * 16 + a_row) * PITCHB + (ks * 2 + a_ch) * 16;
                ldsm4(ah[mt][0], ah[mt][1], ah[mt][2], ah[mt][3], sA + off);
            }
            #pragma unroll
            for (int np = 0; np < 2; np++) {
                uint32_t off = (uint32_t)(wn * 32 + np * 16 + b_row) * PITCHB + (ks * 2 + b_ch) * 16;
                ldsm4(bh[np][0], bh[np][1], bh[np][2], bh[np][3], sB + off);
            }
            #pragma unroll
            for (int mt = 0; mt < 4; mt++)
                #pragma unroll
                for (int np = 0; np < 2; np++)
                    #pragma unroll
                    for (int half = 0; half < 2; half++)
                        mma16816(acc[mt][np * 2 + half], ah[mt], &bh[np][half * 2]);
        }
        __syncthreads();
        if (kb + 2 < NKB) load_stage(kb + 2, kb & 1);
    }

    #pragma unroll
    for (int mt = 0; mt < 4; mt++) {
        #pragma unroll
        for (int nt = 0; nt < 4; nt++) {
            #pragma unroll
            for (int rp = 0; rp < 2; rp++) {
                int row = by * 128 + wm * 64 + mt * 16 + (lane >> 2) + rp * 8;
                int col = bx * 128 + wn * 32 + nt * 8 + (lane & 3) * 2;
                float v0 = acc[mt][nt][rp * 2], v1 = acc[mt][nt][rp * 2 + 1];
                if (MODE == 0) {
                    int which = col >> 10, h = (col >> 6) & 15, d0 = col & 63;
                    int bb = row >> 12, s = row & 4095;
                    __half* base = (which == 0) ? g_qh : (which == 1) ? g_kh : g_vh;
                    if (which == 0) { v0 *= 0.125f; v1 *= 0.125f; }
                    *(__half2*)&base[(((size_t)(bb * HEADS + h)) * SEQ + s) * DHEAD + d0] =
                        __floats2half2_rn(v0, v1);
                } else {
                    *(float2*)&C[(size_t)row * DIMM + col] = make_float2(v0, v1);
                }
            }
        }
    }
}

__global__ void gates_kernel(const float* __restrict__ Wg, const float* __restrict__ bg) {
    int row = blockIdx.x;
    int t = threadIdx.x;
    int h = t >> 3, lane8 = t & 7;
    const __half* xr = g_xn_h + (size_t)row * DIMM;
    float sum = 0.f;
    for (int j = lane8; j < DIMM; j += 8) sum += __half2float(xr[j]) * Wg[j * HEADS + h];
    sum += __shfl_down_sync(0xffffffffu, sum, 4, 8);
    sum += __shfl_down_sync(0xffffffffu, sum, 2, 8);
    sum += __shfl_down_sync(0xffffffffu, sum, 1, 8);
    if (lane8 == 0) {
        float v = sum + bg[h];
        g_gate[row * HEADS + h] = 1.f / (1.f + __expf(-v));
    }
}

__global__ __launch_bounds__(128) void attn_kernel() {
    const int tile = blockIdx.x, h = blockIdx.y, bb = blockIdx.z;
    const int q0 = tile * 64;
    const int tid = threadIdx.x, w = tid >> 5, l = tid & 31;

    __shared__ __half Qs[64 * 64];
    __shared__ __half Ks[64 * 64];
    __shared__ __half Vs[64 * 64];
    const uint32_t qb = smem_u32(Qs), kb = smem_u32(Ks), vb = smem_u32(Vs);

    const size_t base = ((size_t)(bb * HEADS + h)) * SEQ * DHEAD;

    #pragma unroll
    for (int i = 0; i < 4; i++) {
        int idx = tid + i * 128;
        int row = idx >> 3, c16 = idx & 7;
        uint32_t bo = row * 128 + c16 * 16;
        cp16(qb + (bo ^ ((bo >> 3) & 0x70)), g_qh + base + (size_t)(q0 + row) * DHEAD + c16 * 8);
    }
    CP_COMMIT(); CP_WAIT0();
    __syncthreads();

    const int t8 = l >> 3, r8 = l & 7;
    uint32_t qf[4][4];
    #pragma unroll
    for (int kc = 0; kc < 4; kc++) {
        uint32_t bo = (uint32_t)(16 * w + (t8 & 1) * 8 + r8) * 128 + kc * 32 + (t8 >> 1) * 16;
        ldsm4(qf[kc][0], qf[kc][1], qf[kc][2], qf[kc][3], qb + (bo ^ ((bo >> 3) & 0x70)));
    }

    float o[8][4];
    #pragma unroll
    for (int nt = 0; nt < 8; nt++)
        #pragma unroll
        for (int e = 0; e < 4; e++) o[nt][e] = 0.f;
    float m0 = -1e30f, m1 = -1e30f, l0 = 0.f, l1 = 0.f;
    const int i0 = 16 * w + (l >> 2), i1 = i0 + 8;

    for (int c = 0; c < 5; c++) {
        int ks = q0 - 256 + c * 64;
        if (ks < 0) continue;
        __syncthreads();
        #pragma unroll
        for (int i = 0; i < 4; i++) {
            int idx = tid + i * 128;
            int row = idx >> 3, c16 = idx & 7;
            uint32_t bo = row * 128 + c16 * 16;
            uint32_t sw = bo ^ ((bo >> 3) & 0x70);
            const size_t go = base + (size_t)(ks + row) * DHEAD + c16 * 8;
            cp16(kb + sw, g_kh + go);
            cp16(vb + sw, g_vh + go);
        }
        CP_COMMIT(); CP_WAIT0();
        __syncthreads();

        float s[8][4];
        #pragma unroll
        for (int nt = 0; nt < 8; nt++)
            #pragma unroll
            for (int e = 0; e < 4; e++) s[nt][e] = 0.f;
        #pragma unroll
        for (int kc = 0; kc < 4; kc++) {
            #pragma unroll
            for (int g = 0; g < 4; g++) {
                uint32_t t0, t1, t2, t3;
                uint32_t bo = (uint32_t)(g * 16 + ((t8 >= 2) ? 8 : 0) + r8) * 128 + kc * 32 + (t8 & 1) * 16;
                ldsm4(t0, t1, t2, t3, kb + (bo ^ ((bo >> 3) & 0x70)));
                uint32_t b0[2] = {t0, t1}, b1[2] = {t2, t3};
                mma16816(s[2 * g],     qf[kc], b0);
                mma16816(s[2 * g + 1], qf[kc], b1);
            }
        }

        if (c == 0 || c == 4) {
            #pragma unroll
            for (int nt = 0; nt < 8; nt++) {
                #pragma unroll
                for (int e = 0; e < 4; e++) {
                    int j = 8 * nt + 2 * (l & 3) + (e & 1);
                    int i = (e < 2) ? i0 : i1;
                    bool valid = (c == 0) ? (j >= i) : (j <= i);
                    if (!valid) s[nt][e] = -1e30f;
                }
            }
        }

        float mr0 = -1e30f, mr1 = -1e30f;
        #pragma unroll
        for (int nt = 0; nt < 8; nt++) {
            mr0 = fmaxf(mr0, fmaxf(s[nt][0], s[nt][1]));
            mr1 = fmaxf(mr1, fmaxf(s[nt][2], s[nt][3]));
        }
        mr0 = fmaxf(mr0, __shfl_xor_sync(0xffffffffu, mr0, 1));
        mr0 = fmaxf(mr0, __shfl_xor_sync(0xffffffffu, mr0, 2));
        mr1 = fmaxf(mr1, __shfl_xor_sync(0xffffffffu, mr1, 1));
        mr1 = fmaxf(mr1, __shfl_xor_sync(0xffffffffu, mr1, 2));
        float mn0 = fmaxf(m0, mr0), mn1 = fmaxf(m1, mr1);
        float cr0 = __expf(m0 - mn0), cr1 = __expf(m1 - mn1);
        l0 *= cr0; l1 *= cr1;
        #pragma unroll
        for (int nt = 0; nt < 8; nt++) {
            o[nt][0] *= cr0; o[nt][1] *= cr0; o[nt][2] *= cr1; o[nt][3] *= cr1;
        }
        #pragma unroll
        for (int nt = 0; nt < 8; nt++) {
            s[nt][0] = __expf(s[nt][0] - mn0);
            s[nt][1] = __expf(s[nt][1] - mn0);
            s[nt][2] = __expf(s[nt][2] - mn1);
            s[nt][3] = __expf(s[nt][3] - mn1);
            l0 += s[nt][0] + s[nt][1];
            l1 += s[nt][2] + s[nt][3];
        }
        m0 = mn0; m1 = mn1;

        #pragma unroll
        for (int kc = 0; kc < 4; kc++) {
            uint32_t a[4];
            a[0] = packh2(s[2*kc][0],   s[2*kc][1]);
            a[1] = packh2(s[2*kc][2],   s[2*kc][3]);
            a[2] = packh2(s[2*kc+1][0], s[2*kc+1][1]);
            a[3] = packh2(s[2*kc+1][2], s[2*kc+1][3]);
            #pragma unroll
            for (int ng = 0; ng < 4; ng++) {
                uint32_t t0, t1, t2, t3;
                uint32_t bo = (uint32_t)(kc * 16 + ((t8 & 1) ? 8 : 0) + r8) * 128 + ng * 32 + ((t8 >= 2) ? 16 : 0);
                ldsm4t(t0, t1, t2, t3, vb + (bo ^ ((bo >> 3) & 0x70)));
                uint32_t b0[2] = {t0, t1}, b1[2] = {t2, t3};
                mma16816(o[2 * ng],     a, b0);
                mma16816(o[2 * ng + 1], a, b1);
            }
        }
    }

    l0 += __shfl_xor_sync(0xffffffffu, l0, 1);
    l0 += __shfl_xor_sync(0xffffffffu, l0, 2);
    l1 += __shfl_xor_sync(0xffffffffu, l1, 1);
    l1 += __shfl_xor_sync(0xffffffffu, l1, 2);

    int rg0 = bb * SEQ + q0 + i0, rg1 = rg0 + 8;
    float inv0 = g_gate[rg0 * HEADS + h] / l0;
    float inv1 = g_gate[rg1 * HEADS + h] / l1;
    #pragma unroll
    for (int nt = 0; nt < 8; nt++) {
        int d = 8 * nt + 2 * (l & 3);
        *(__half2*)&g_attn_h[(size_t)rg0 * DINNER + h * DHEAD + d] =
            __floats2half2_rn(o[nt][0] * inv0, o[nt][1] * inv0);
        *(__half2*)&g_attn_h[(size_t)rg1 * DINNER + h * DHEAD + d] =
            __floats2half2_rn(o[nt][2] * inv1, o[nt][3] * inv1);
    }
}

extern "C" void kernel_launch(void* const* d_in, const int* in_sizes, int n_in,
                              void* d_out, int out_size) {
    const float* x     = (const float*)d_in[0];
    const float* gamma = (const float*)d_in[1];
    const float* Wqkv  = (const float*)d_in[2];
    const float* Wg    = (const float*)d_in[3];
    const float* bg    = (const float*)d_in[4];
    const float* Wout  = (const float*)d_in[5];

    __half *xn_h, *wqkv_h, *wout_h, *attn_h;
    cudaGetSymbolAddress((void**)&xn_h,   g_xn_h);
    cudaGetSymbolAddress((void**)&wqkv_h, g_wqkv_h);
    cudaGetSymbolAddress((void**)&wout_h, g_wout_h);
    cudaGetSymbolAddress((void**)&attn_h, g_attn_h);

    cudaFuncSetAttribute(mma_gemm_kernel<0>, cudaFuncAttributeMaxDynamicSharedMemorySize, GSMEM_TOTAL);
    cudaFuncSetAttribute(mma_gemm_kernel<1>, cudaFuncAttributeMaxDynamicSharedMemorySize, GSMEM_TOTAL);

    transpose_h<<<dim3(3 * DINNER / 32, DIMM / 32), dim3(32, 8)>>>(Wqkv, wqkv_h, 3 * DINNER);
    transpose_h<<<dim3(DIMM / 32, DIMM / 32), dim3(32, 8)>>>(Wout, wout_h, DIMM);
    rms_kernel<<<ROWS, 256>>>(x, gamma);
    mma_gemm_kernel<0><<<dim3(3 * DINNER / 128, ROWS / 128), 256, GSMEM_TOTAL>>>(
        xn_h, wqkv_h, nullptr);
    gates_kernel<<<ROWS, 128>>>(Wg, bg);
    attn_kernel<<<dim3(SEQ / 64, HEADS, BATCH), 128>>>();
    mma_gemm_kernel<1><<<dim3(DIMM / 128, ROWS / 128), 256, GSMEM_TOTAL>>>(
        attn_h, wout_h, (float*)d_out);
}

// round 11
// speedup vs baseline: 5.2513x; 1.0356x over previous
#include <cuda_runtime.h>
#include <cuda_fp16.h>
#include <cstdint>

#define BATCH   2
#define SEQ     4096
#define DIMM    1024
#define HEADS   16
#define DHEAD   64
#define ROWS    (BATCH*SEQ)
#define DINNER  (HEADS*DHEAD)

__device__ __half g_xn_h[ROWS * DIMM];
__device__ __half g_qh[BATCH * HEADS * SEQ * DHEAD];
__device__ __half g_kh[BATCH * HEADS * SEQ * DHEAD];
__device__ __half g_vh[BATCH * HEADS * SEQ * DHEAD];
__device__ float  g_gate[ROWS * HEADS];
__device__ __half g_attn_h[ROWS * DINNER];
__device__ __half g_wqkv_h[3 * DINNER * DIMM];
__device__ __half g_wout_h[DIMM * DINNER];

__device__ __forceinline__ uint32_t smem_u32(const void* p) {
    uint32_t a;
    asm("{ .reg .u64 t; cvta.to.shared.u64 t, %1; cvt.u32.u64 %0, t; }" : "=r"(a) : "l"(p));
    return a;
}
__device__ __forceinline__ void cp16(uint32_t s, const void* g) {
    asm volatile("cp.async.cg.shared.global [%0], [%1], 16;" :: "r"(s), "l"(g));
}
#define CP_COMMIT() asm volatile("cp.async.commit_group;" ::: "memory")
#define CP_WAIT2()  asm volatile("cp.async.wait_group 2;" ::: "memory")
#define CP_WAIT1()  asm volatile("cp.async.wait_group 1;" ::: "memory")
#define CP_WAIT0()  asm volatile("cp.async.wait_group 0;" ::: "memory")

__device__ __forceinline__ void ldsm4(uint32_t& r0, uint32_t& r1, uint32_t& r2, uint32_t& r3, uint32_t a) {
    asm volatile("ldmatrix.sync.aligned.m8n8.x4.shared.b16 {%0,%1,%2,%3}, [%4];"
                 : "=r"(r0), "=r"(r1), "=r"(r2), "=r"(r3) : "r"(a));
}
__device__ __forceinline__ void ldsm4t(uint32_t& r0, uint32_t& r1, uint32_t& r2, uint32_t& r3, uint32_t a) {
    asm volatile("ldmatrix.sync.aligned.m8n8.x4.trans.shared.b16 {%0,%1,%2,%3}, [%4];"
                 : "=r"(r0), "=r"(r1), "=r"(r2), "=r"(r3) : "r"(a));
}
__device__ __forceinline__ void mma16816(float* d, const uint32_t* a, const uint32_t* b) {
    asm volatile("mma.sync.aligned.m16n8k16.row.col.f32.f16.f16.f32 "
                 "{%0,%1,%2,%3}, {%4,%5,%6,%7}, {%8,%9}, {%0,%1,%2,%3};"
                 : "+f"(d[0]), "+f"(d[1]), "+f"(d[2]), "+f"(d[3])
                 : "r"(a[0]), "r"(a[1]), "r"(a[2]), "r"(a[3]), "r"(b[0]), "r"(b[1]));
}
__device__ __forceinline__ uint32_t packh2(float a, float b) {
    __half2 h = __floats2half2_rn(a, b);
    return *(uint32_t*)&h;
}

__global__ void rms_kernel(const float* __restrict__ x, const float* __restrict__ gamma) {
    int row = blockIdx.x;
    int t = threadIdx.x;
    const float4* xr = (const float4*)(x + (size_t)row * DIMM);
    float4 a = xr[t];
    float ss = a.x*a.x + a.y*a.y + a.z*a.z + a.w*a.w;
    #pragma unroll
    for (int o = 16; o > 0; o >>= 1) ss += __shfl_down_sync(0xffffffffu, ss, o);
    __shared__ float red[8];
    __shared__ float snorm;
    if ((t & 31) == 0) red[t >> 5] = ss;
    __syncthreads();
    if (t == 0) {
        float s = 0.f;
        #pragma unroll
        for (int i = 0; i < 8; i++) s += red[i];
        snorm = 32.0f / fmaxf(sqrtf(s), 1e-12f);
    }
    __syncthreads();
    float sc = snorm;
    float4 g = ((const float4*)gamma)[t];
    __half2* ph = (__half2*)(g_xn_h + (size_t)row * DIMM);
    ph[2*t]   = __floats2half2_rn(a.x * sc * g.x, a.y * sc * g.y);
    ph[2*t+1] = __floats2half2_rn(a.z * sc * g.z, a.w * sc * g.w);
}

__global__ void transpose_h(const float* __restrict__ W, __half* __restrict__ out, int N) {
    __shared__ float t[32][33];
    int tx = threadIdx.x, ty = threadIdx.y;
    int x = blockIdx.x * 32 + tx;
    int y0 = blockIdx.y * 32;
    #pragma unroll
    for (int r = ty; r < 32; r += 8)
        t[r][tx] = W[(size_t)(y0 + r) * N + x];
    __syncthreads();
    #pragma unroll
    for (int r = 0; r < 4; r++) {
        int a = ty + r * 8;
        out[(size_t)(blockIdx.x * 32 + a) * DIMM + y0 + tx] = __float2half_rn(t[tx][a]);
    }
}

#define PITCHB      80
#define MAT_BYTES   (128 * PITCHB)
#define STG_BYTES   (2 * MAT_BYTES)
#define NSTAGE      4
#define GSMEM_TOTAL (NSTAGE * STG_BYTES)

template<int MODE>
__global__ __launch_bounds__(256) void mma_gemm_kernel(
    const __half* __restrict__ A, const __half* __restrict__ B,
    float* __restrict__ C)
{
    extern __shared__ char smem[];
    const uint32_t sb = smem_u32(smem);
    const int tid = threadIdx.x;
    const int lane = tid & 31, wid = tid >> 5;
    const int wm = wid >> 2, wn = wid & 3;
    const int bx = blockIdx.x, by = blockIdx.y;

    const __half* gmat[2] = {A + (size_t)(by * 128) * DIMM, B + (size_t)(bx * 128) * DIMM};

    int ld_mat[4], ld_row[4], ld_ch[4];
    #pragma unroll
    for (int i = 0; i < 4; i++) {
        int idx = tid + i * 256;
        ld_mat[i] = idx >> 9;
        int rem = idx & 511;
        ld_row[i] = rem >> 2;
        ld_ch[i]  = rem & 3;
    }

    float acc[4][4][4];
    #pragma unroll
    for (int mt = 0; mt < 4; mt++)
        #pragma unroll
        for (int nt = 0; nt < 4; nt++)
            #pragma unroll
            for (int r = 0; r < 4; r++) acc[mt][nt][r] = 0.f;

    const int quad = lane >> 3, l7 = lane & 7;
    const int a_row = (quad & 1) * 8 + l7;
    const int a_ch  = quad >> 1;
    const int b_row = (quad >> 1) * 8 + l7;
    const int b_ch  = quad & 1;

    auto load_stage = [&](int kb, int buf) {
        uint32_t s0 = sb + buf * STG_BYTES;
        #pragma unroll
        for (int i = 0; i < 4; i++) {
            const __half* g = gmat[ld_mat[i]] + (size_t)ld_row[i] * DIMM + kb * 32 + ld_ch[i] * 8;
            cp16(s0 + ld_mat[i] * MAT_BYTES + ld_row[i] * PITCHB + ld_ch[i] * 16, g);
        }
        CP_COMMIT();
    };

    load_stage(0, 0);
    load_stage(1, 1);
    load_stage(2, 2);

    const int NKB = DIMM / 32;
    for (int kb = 0; kb < NKB; kb++) {
        CP_WAIT2();
        __syncthreads();
        if (kb + 3 < NKB) load_stage(kb + 3, (kb + 3) & (NSTAGE - 1));
        else CP_COMMIT();
        const uint32_t s0 = sb + (kb & (NSTAGE - 1)) * STG_BYTES;
        const uint32_t sA = s0, sB = s0 + MAT_BYTES;

        #pragma unroll
        for (int ks = 0; ks < 2; ks++) {
            uint32_t ah[4][4], bh[2][4];
            #pragma unroll
            for (int mt = 0; mt < 4; mt++) {
                uint32_t off = (uint32_t)(wm * 64 + mt * 16 + a_row) * PITCHB + (ks * 2 + a_ch) * 16;
                ldsm4(ah[mt][0], ah[mt][1], ah[mt][2], ah[mt][3], sA + off);
            }
            #pragma unroll
            for (int np = 0; np < 2; np++) {
                uint32_t off = (uint32_t)(wn * 32 + np * 16 + b_row) * PITCHB + (ks * 2 + b_ch) * 16;
                ldsm4(bh[np][0], bh[np][1], bh[np][2], bh[np][3], sB + off);
            }
            #pragma unroll
            for (int mt = 0; mt < 4; mt++)
                #pragma unroll
                for (int np = 0; np < 2; np++)
                    #pragma unroll
                    for (int half = 0; half < 2; half++)
                        mma16816(acc[mt][np * 2 + half], ah[mt], &bh[np][half * 2]);
        }
    }

    #pragma unroll
    for (int mt = 0; mt < 4; mt++) {
        #pragma unroll
        for (int nt = 0; nt < 4; nt++) {
            #pragma unroll
            for (int rp = 0; rp < 2; rp++) {
                int row = by * 128 + wm * 64 + mt * 16 + (lane >> 2) + rp * 8;
                int col = bx * 128 + wn * 32 + nt * 8 + (lane & 3) * 2;
                float v0 = acc[mt][nt][rp * 2], v1 = acc[mt][nt][rp * 2 + 1];
                if (MODE == 0) {
                    int which = col >> 10, h = (col >> 6) & 15, d0 = col & 63;
                    int bb = row >> 12, s = row & 4095;
                    __half* base = (which == 0) ? g_qh : (which == 1) ? g_kh : g_vh;
                    if (which == 0) { v0 *= 0.125f; v1 *= 0.125f; }
                    *(__half2*)&base[(((size_t)(bb * HEADS + h)) * SEQ + s) * DHEAD + d0] =
                        __floats2half2_rn(v0, v1);
                } else {
                    *(float2*)&C[(size_t)row * DIMM + col] = make_float2(v0, v1);
                }
            }
        }
    }
}

__global__ void gates_kernel(const float* __restrict__ Wg, const float* __restrict__ bg) {
    int row = blockIdx.x;
    int t = threadIdx.x;
    int h = t >> 3, lane8 = t & 7;
    const __half* xr = g_xn_h + (size_t)row * DIMM;
    float sum = 0.f;
    for (int j = lane8; j < DIMM; j += 8) sum += __half2float(xr[j]) * Wg[j * HEADS + h];
    sum += __shfl_down_sync(0xffffffffu, sum, 4, 8);
    sum += __shfl_down_sync(0xffffffffu, sum, 2, 8);
    sum += __shfl_down_sync(0xffffffffu, sum, 1, 8);
    if (lane8 == 0) {
        float v = sum + bg[h];
        g_gate[row * HEADS + h] = 1.f / (1.f + __expf(-v));
    }
}

__global__ __launch_bounds__(128) void attn_kernel() {
    const int tile = blockIdx.x, h = blockIdx.y, bb = blockIdx.z;
    const int q0 = tile * 64;
    const int tid = threadIdx.x, w = tid >> 5, l = tid & 31;

    __shared__ __half Qs[64 * 64];
    __shared__ __half KVs[2][2][64 * 64];   // [buf][0=K,1=V]
    const uint32_t qb = smem_u32(Qs);

    const size_t base = ((size_t)(bb * HEADS + h)) * SEQ * DHEAD;
    const int cstart = (q0 >= 256) ? 0 : ((256 - q0) >> 6);

    // Q load (group 1)
    #pragma unroll
    for (int i = 0; i < 4; i++) {
        int idx = tid + i * 128;
        int row = idx >> 3, c16 = idx & 7;
        uint32_t bo = row * 128 + c16 * 16;
        cp16(qb + (bo ^ ((bo >> 3) & 0x70)), g_qh + base + (size_t)(q0 + row) * DHEAD + c16 * 8);
    }
    CP_COMMIT();

    // KV prologue: chunk cstart -> buf 0 (group 2)
    {
        const int ks = q0 - 256 + cstart * 64;
        const uint32_t kbb = smem_u32(&KVs[0][0][0]);
        const uint32_t vbb = smem_u32(&KVs[0][1][0]);
        #pragma unroll
        for (int i = 0; i < 4; i++) {
            int idx = tid + i * 128;
            int row = idx >> 3, c16 = idx & 7;
            uint32_t bo = row * 128 + c16 * 16;
            uint32_t sw = bo ^ ((bo >> 3) & 0x70);
            const size_t go = base + (size_t)(ks + row) * DHEAD + c16 * 8;
            cp16(kbb + sw, g_kh + go);
            cp16(vbb + sw, g_vh + go);
        }
        CP_COMMIT();
    }

    // wait for Q only (KV may still be in flight), build Q fragments
    CP_WAIT1();
    __syncthreads();
    const int t8 = l >> 3, r8 = l & 7;
    uint32_t qf[4][4];
    #pragma unroll
    for (int kc = 0; kc < 4; kc++) {
        uint32_t bo = (uint32_t)(16 * w + (t8 & 1) * 8 + r8) * 128 + kc * 32 + (t8 >> 1) * 16;
        ldsm4(qf[kc][0], qf[kc][1], qf[kc][2], qf[kc][3], qb + (bo ^ ((bo >> 3) & 0x70)));
    }

    float o[8][4];
    #pragma unroll
    for (int nt = 0; nt < 8; nt++)
        #pragma unroll
        for (int e = 0; e < 4; e++) o[nt][e] = 0.f;
    float m0 = -1e30f, m1 = -1e30f, l0 = 0.f, l1 = 0.f;
    const int i0 = 16 * w + (l >> 2), i1 = i0 + 8;

    for (int c = cstart; c < 5; c++) {
        const int buf = (c - cstart) & 1;
        const uint32_t kbb = smem_u32(&KVs[buf][0][0]);
        const uint32_t vbb = smem_u32(&KVs[buf][1][0]);

        __syncthreads();                    // all warps done with buf^1 compute
        if (c + 1 < 5) {                    // prefetch next chunk into buf^1
            const int ksn = q0 - 256 + (c + 1) * 64;
            const uint32_t kbn = smem_u32(&KVs[buf ^ 1][0][0]);
            const uint32_t vbn = smem_u32(&KVs[buf ^ 1][1][0]);
            #pragma unroll
            for (int i = 0; i < 4; i++) {
                int idx = tid + i * 128;
                int row = idx >> 3, c16 = idx & 7;
                uint32_t bo = row * 128 + c16 * 16;
                uint32_t sw = bo ^ ((bo >> 3) & 0x70);
                const size_t go = base + (size_t)(ksn + row) * DHEAD + c16 * 8;
                cp16(kbn + sw, g_kh + go);
                cp16(vbn + sw, g_vh + go);
            }
            CP_COMMIT();
            CP_WAIT1();
        } else {
            CP_WAIT0();
        }
        __syncthreads();

        float s[8][4];
        #pragma unroll
        for (int nt = 0; nt < 8; nt++)
            #pragma unroll
            for (int e = 0; e < 4; e++) s[nt][e] = 0.f;
        #pragma unroll
        for (int kc = 0; kc < 4; kc++) {
            #pragma unroll
            for (int g = 0; g < 4; g++) {
                uint32_t t0, t1, t2, t3;
                uint32_t bo = (uint32_t)(g * 16 + ((t8 >= 2) ? 8 : 0) + r8) * 128 + kc * 32 + (t8 & 1) * 16;
                ldsm4(t0, t1, t2, t3, kbb + (bo ^ ((bo >> 3) & 0x70)));
                uint32_t b0[2] = {t0, t1}, b1[2] = {t2, t3};
                mma16816(s[2 * g],     qf[kc], b0);
                mma16816(s[2 * g + 1], qf[kc], b1);
            }
        }

        if (c == 0 || c == 4) {
            #pragma unroll
            for (int nt = 0; nt < 8; nt++) {
                #pragma unroll
                for (int e = 0; e < 4; e++) {
                    int j = 8 * nt + 2 * (l & 3) + (e & 1);
                    int i = (e < 2) ? i0 : i1;
                    bool valid = (c == 0) ? (j >= i) : (j <= i);
                    if (!valid) s[nt][e] = -1e30f;
                }
            }
        }

        float mr0 = -1e30f, mr1 = -1e30f;
        #pragma unroll
        for (int nt = 0; nt < 8; nt++) {
            mr0 = fmaxf(mr0, fmaxf(s[nt][0], s[nt][1]));
            mr1 = fmaxf(mr1, fmaxf(s[nt][2], s[nt][3]));
        }
        mr0 = fmaxf(mr0, __shfl_xor_sync(0xffffffffu, mr0, 1));
        mr0 = fmaxf(mr0, __shfl_xor_sync(0xffffffffu, mr0, 2));
        mr1 = fmaxf(mr1, __shfl_xor_sync(0xffffffffu, mr1, 1));
        mr1 = fmaxf(mr1, __shfl_xor_sync(0xffffffffu, mr1, 2));
        float mn0 = fmaxf(m0, mr0), mn1 = fmaxf(m1, mr1);
        float cr0 = __expf(m0 - mn0), cr1 = __expf(m1 - mn1);
        l0 *= cr0; l1 *= cr1;
        #pragma unroll
        for (int nt = 0; nt < 8; nt++) {
            o[nt][0] *= cr0; o[nt][1] *= cr0; o[nt][2] *= cr1; o[nt][3] *= cr1;
        }
        #pragma unroll
        for (int nt = 0; nt < 8; nt++) {
            s[nt][0] = __expf(s[nt][0] - mn0);
            s[nt][1] = __expf(s[nt][1] - mn0);
            s[nt][2] = __expf(s[nt][2] - mn1);
            s[nt][3] = __expf(s[nt][3] - mn1);
            l0 += s[nt][0] + s[nt][1];
            l1 += s[nt][2] + s[nt][3];
        }
        m0 = mn0; m1 = mn1;

        #pragma unroll
        for (int kc = 0; kc < 4; kc++) {
            uint32_t a[4];
            a[0] = packh2(s[2*kc][0],   s[2*kc][1]);
            a[1] = packh2(s[2*kc][2],   s[2*kc][3]);
            a[2] = packh2(s[2*kc+1][0], s[2*kc+1][1]);
            a[3] = packh2(s[2*kc+1][2], s[2*kc+1][3]);
            #pragma unroll
            for (int ng = 0; ng < 4; ng++) {
                uint32_t t0, t1, t2, t3;
                uint32_t bo = (uint32_t)(kc * 16 + ((t8 & 1) ? 8 : 0) + r8) * 128 + ng * 32 + ((t8 >= 2) ? 16 : 0);
                ldsm4t(t0, t1, t2, t3, vbb + (bo ^ ((bo >> 3) & 0x70)));
                uint32_t b0[2] = {t0, t1}, b1[2] = {t2, t3};
                mma16816(o[2 * ng],     a, b0);
                mma16816(o[2 * ng + 1], a, b1);
            }
        }
    }

    l0 += __shfl_xor_sync(0xffffffffu, l0, 1);
    l0 += __shfl_xor_sync(0xffffffffu, l0, 2);
    l1 += __shfl_xor_sync(0xffffffffu, l1, 1);
    l1 += __shfl_xor_sync(0xffffffffu, l1, 2);

    int rg0 = bb * SEQ + q0 + i0, rg1 = rg0 + 8;
    float inv0 = g_gate[rg0 * HEADS + h] / l0;
    float inv1 = g_gate[rg1 * HEADS + h] / l1;
    #pragma unroll
    for (int nt = 0; nt < 8; nt++) {
        int d = 8 * nt + 2 * (l & 3);
        *(__half2*)&g_attn_h[(size_t)rg0 * DINNER + h * DHEAD + d] =
            __floats2half2_rn(o[nt][0] * inv0, o[nt][1] * inv0);
        *(__half2*)&g_attn_h[(size_t)rg1 * DINNER + h * DHEAD + d] =
            __floats2half2_rn(o[nt][2] * inv1, o[nt][3] * inv1);
    }
}

extern "C" void kernel_launch(void* const* d_in, const int* in_sizes, int n_in,
                              void* d_out, int out_size) {
    const float* x     = (const float*)d_in[0];
    const float* gamma = (const float*)d_in[1];
    const float* Wqkv  = (const float*)d_in[2];
    const float* Wg    = (const float*)d_in[3];
    const float* bg    = (const float*)d_in[4];
    const float* Wout  = (const float*)d_in[5];

    __half *xn_h, *wqkv_h, *wout_h, *attn_h;
    cudaGetSymbolAddress((void**)&xn_h,   g_xn_h);
    cudaGetSymbolAddress((void**)&wqkv_h, g_wqkv_h);
    cudaGetSymbolAddress((void**)&wout_h, g_wout_h);
    cudaGetSymbolAddress((void**)&attn_h, g_attn_h);

    cudaFuncSetAttribute(mma_gemm_kernel<0>, cudaFuncAttributeMaxDynamicSharedMemorySize, GSMEM_TOTAL);
    cudaFuncSetAttribute(mma_gemm_kernel<1>, cudaFuncAttributeMaxDynamicSharedMemorySize, GSMEM_TOTAL);

    transpose_h<<<dim3(3 * DINNER / 32, DIMM / 32), dim3(32, 8)>>>(Wqkv, wqkv_h, 3 * DINNER);
    transpose_h<<<dim3(DIMM / 32, DIMM / 32), dim3(32, 8)>>>(Wout, wout_h, DIMM);
    rms_kernel<<<ROWS, 256>>>(x, gamma);
    mma_gemm_kernel<0><<<dim3(3 * DINNER / 128, ROWS / 128), 256, GSMEM_TOTAL>>>(
        xn_h, wqkv_h, nullptr);
    gates_kernel<<<ROWS, 128>>>(Wg, bg);
    attn_kernel<<<dim3(SEQ / 64, HEADS, BATCH), 128>>>();
    mma_gemm_kernel<1><<<dim3(DIMM / 128, ROWS / 128), 256, GSMEM_TOTAL>>>(
        attn_h, wout_h, (float*)d_out);
}